// round 8
// baseline (speedup 1.0000x reference)
#include <cuda_runtime.h>
#include <math.h>
#include <stdint.h>

#define NTOK 65536
#define CIN 192
#define HID 384
#define OUTD 192
#define NE 8
#define KCAP 10240
#define TTILE 64
#define SSTR 66
#define LSCALE 2.0f  /* alpha/r = 16/8 */

typedef unsigned long long ull;

__device__ __forceinline__ ull pk2(float lo, float hi) {
    ull r; asm("mov.b64 %0,{%1,%2};" : "=l"(r) : "f"(lo), "f"(hi)); return r;
}
__device__ __forceinline__ void upk2(ull v, float& lo, float& hi) {
    asm("mov.b64 {%0,%1},%2;" : "=f"(lo), "=f"(hi) : "l"(v));
}
__device__ __forceinline__ void fma2(ull& d, ull a, ull b) {
    asm("fma.rn.f32x2 %0,%1,%2,%0;" : "+l"(d) : "l"(a), "l"(b));
}

// ---------------- device scratch ----------------
__device__ float    g_logits[NE * NTOK];
__device__ unsigned g_mask[NTOK];
__device__ int      g_cnt[NE];
__device__ int      g_list[NE * NTOK];
__device__ float    g_wl[NE * NTOK];
__device__ unsigned g_te[NTOK];
__device__ float    g_tw0[NTOK];
__device__ float    g_tw1[NTOK];

__global__ void init_kernel() {
    if (threadIdx.x < NE) g_cnt[threadIdx.x] = 0;
}

// ---------------- gate: features + LN + logits ----------------
__global__ void __launch_bounds__(1024) gate_kernel(
    const float* __restrict__ x, const float* __restrict__ xprev,
    const float* __restrict__ Wz, const float* __restrict__ lng,
    const float* __restrict__ lnb, const float* __restrict__ Wg,
    const float* __restrict__ bg)
{
    extern __shared__ float sm[];
    float* sWz = sm;            // 12288
    float* sWg = sWz + 12288;   // 258*9 = 2322 (stride-9 padded, conflict-free)
    float* sg  = sWg + 2322;    // 258
    float* sb  = sg + 258;      // 258
    float* sbg = sb + 258;      // 8
    float* sX  = sbg + 8;       // 32*192

    int tid = threadIdx.x, lane = tid & 31, warp = tid >> 5;
    int n = blockIdx.x * 32 + warp;

    for (int i = tid; i < 12288; i += 1024) sWz[i] = Wz[i];
    for (int i = tid; i < 2064;  i += 1024) sWg[(i >> 3)*9 + (i & 7)] = Wg[i];
    for (int i = tid; i < 258;   i += 1024) { sg[i] = lng[i]; sb[i] = lnb[i]; }
    if (tid < 8) sbg[tid] = bg[tid];

    float xr[6];
    #pragma unroll
    for (int i = 0; i < 6; i++) {
        xr[i] = x[(size_t)n*CIN + lane + 32*i];
        sX[warp*CIN + lane + 32*i] = xr[i];
    }
    float s = 0.f, ss = 0.f;
    #pragma unroll
    for (int i = 0; i < 6; i++) {
        float a = fabsf(xr[i] - xprev[(size_t)n*CIN + lane + 32*i]);
        s += a; ss += a*a;
    }
    #pragma unroll
    for (int o = 16; o; o >>= 1) {
        s  += __shfl_xor_sync(0xffffffffu, s, o);
        ss += __shfl_xor_sync(0xffffffffu, ss, o);
    }
    float dmean = s * (1.0f/192.0f);
    float dvar  = fmaxf((ss - s*dmean) * (1.0f/191.0f), 0.f);
    float mu = log1pf(dmean), sd = log1pf(sqrtf(dvar));

    __syncthreads();

    float z0 = 0.f, z1 = 0.f;
    for (int c = 0; c < CIN; c++) {
        float xv = sX[warp*CIN + c];
        z0 = fmaf(xv, sWz[c*64 + lane],      z0);
        z1 = fmaf(xv, sWz[c*64 + lane + 32], z1);
    }
    float sa = z0 + z1, s2 = z0*z0 + z1*z1;
    #pragma unroll
    for (int i = 0; i < 6; i++) { sa += xr[i]; s2 += xr[i]*xr[i]; }
    if (lane == 0) { sa += mu + sd; s2 += mu*mu + sd*sd; }
    #pragma unroll
    for (int o = 16; o; o >>= 1) {
        sa += __shfl_xor_sync(0xffffffffu, sa, o);
        s2 += __shfl_xor_sync(0xffffffffu, s2, o);
    }
    float m_   = sa * (1.0f/258.0f);
    float rstd = rsqrtf(s2 * (1.0f/258.0f) - m_*m_ + 1e-5f);

    float acc[8] = {0,0,0,0,0,0,0,0};
    #pragma unroll
    for (int i = 0; i < 6; i++) {
        int idx = lane + 32*i;
        float nv = (xr[i] - m_)*rstd*sg[idx] + sb[idx];
        #pragma unroll
        for (int e = 0; e < 8; e++) acc[e] = fmaf(nv, sWg[idx*9 + e], acc[e]);
    }
    {
        int idx = 192 + lane;
        float nv = (z0 - m_)*rstd*sg[idx] + sb[idx];
        #pragma unroll
        for (int e = 0; e < 8; e++) acc[e] = fmaf(nv, sWg[idx*9 + e], acc[e]);
        idx = 224 + lane;
        nv = (z1 - m_)*rstd*sg[idx] + sb[idx];
        #pragma unroll
        for (int e = 0; e < 8; e++) acc[e] = fmaf(nv, sWg[idx*9 + e], acc[e]);
    }
    if (lane == 0) {
        float nv = (mu - m_)*rstd*sg[256] + sb[256];
        #pragma unroll
        for (int e = 0; e < 8; e++) acc[e] = fmaf(nv, sWg[256*9 + e], acc[e]);
        nv = (sd - m_)*rstd*sg[257] + sb[257];
        #pragma unroll
        for (int e = 0; e < 8; e++) acc[e] = fmaf(nv, sWg[257*9 + e], acc[e]);
    }
    #pragma unroll
    for (int e = 0; e < 8; e++) {
        #pragma unroll
        for (int o = 16; o; o >>= 1) acc[e] += __shfl_xor_sync(0xffffffffu, acc[e], o);
    }
    if (lane == 0) {
        #pragma unroll
        for (int e = 0; e < 8; e++) g_logits[e*NTOK + n] = acc[e] + sbg[e];
        g_mask[n] = 0u;
    }
}

// ---------------- expert-choice: radix select top-K per expert ----------------
__device__ __forceinline__ unsigned f2key(float f) {
    unsigned u = __float_as_uint(f);
    return (u & 0x80000000u) ? ~u : (u | 0x80000000u);
}

__global__ void __launch_bounds__(1024) select_kernel() {
    __shared__ unsigned hist[256];
    __shared__ unsigned sh_digit, sh_need;
    __shared__ int ccount[64];
    __shared__ int cbase[64];

    int e = blockIdx.x, tid = threadIdx.x;
    int lane = tid & 31, warp = tid >> 5;
    const float* base = g_logits + (size_t)e * NTOK;

    unsigned prefix = 0, pmask = 0, need = KCAP;
    for (int pass = 0; pass < 4; pass++) {
        int shift = 24 - pass*8;
        if (tid < 256) hist[tid] = 0;
        __syncthreads();
        for (int n = tid; n < NTOK; n += 1024) {
            unsigned k = f2key(base[n]);
            bool act = ((k & pmask) == prefix);
            unsigned dg = act ? ((k >> shift) & 255u) : 0xffffffffu;
            unsigned peers = __match_any_sync(0xffffffffu, dg);
            if (act && (__ffs(peers) - 1) == lane)
                atomicAdd(&hist[dg], (unsigned)__popc(peers));
        }
        __syncthreads();
        if (tid == 0) {
            unsigned cum = 0; int d = 255;
            for (; d > 0; d--) {
                unsigned h = hist[d];
                if (cum + h >= need) break;
                cum += h;
            }
            sh_digit = (unsigned)d;
            sh_need  = need - cum;
        }
        __syncthreads();
        prefix |= sh_digit << shift;
        pmask  |= 0xFFu << shift;
        need    = sh_need;
        __syncthreads();
    }
    unsigned thr = prefix;
    int r = (int)need;

    for (int n = tid; n < NTOK; n += 1024)
        if (f2key(base[n]) > thr) atomicOr(&g_mask[n], 1u << e);

    for (int c = warp; c < 64; c += 32) {
        int cnt = 0;
        for (int s = 0; s < 32; s++) {
            int n = c*1024 + s*32 + lane;
            cnt += (f2key(base[n]) == thr);
        }
        #pragma unroll
        for (int o = 16; o; o >>= 1) cnt += __shfl_xor_sync(0xffffffffu, cnt, o);
        if (lane == 0) ccount[c] = cnt;
    }
    __syncthreads();
    if (tid == 0) {
        int run = 0;
        for (int c = 0; c < 64; c++) { cbase[c] = run; run += ccount[c]; }
    }
    __syncthreads();
    for (int c = warp; c < 64; c += 32) {
        int rank = cbase[c];
        if (rank >= r) continue;
        for (int s = 0; s < 32; s++) {
            int n = c*1024 + s*32 + lane;
            bool p = (f2key(base[n]) == thr);
            unsigned bal = __ballot_sync(0xffffffffu, p);
            int myrank = rank + __popc(bal & ((1u << lane) - 1u));
            if (p && myrank < r) atomicOr(&g_mask[n], 1u << e);
            rank += __popc(bal);
        }
    }
}

// ---------------- routing (block-aggregated dispatch) ----------------
__global__ void __launch_bounds__(256) route_kernel(float* __restrict__ out) {
    __shared__ int sCnt[8], sBase[8];
    int tid = threadIdx.x;
    int n = blockIdx.x * 256 + tid;
    if (tid < 8) sCnt[tid] = 0;
    __syncthreads();

    float l[8];
    #pragma unroll
    for (int e = 0; e < 8; e++) l[e] = g_logits[e*NTOK + n];
    unsigned m = g_mask[n];
    if (m == 0u) {
        int best = 0; float bv = l[0];
        #pragma unroll
        for (int e = 1; e < 8; e++) if (l[e] > bv) { bv = l[e]; best = e; }
        m = 1u << best;
    }
    int e0 = -1, e1 = -1; float v0 = -INFINITY, v1 = -INFINITY;
    #pragma unroll
    for (int e = 0; e < 8; e++) {
        if ((m >> e) & 1u) {
            float f = l[e];
            if (f > v0)      { v1 = v0; e1 = e0; v0 = f; e0 = e; }
            else if (f > v1) { v1 = f; e1 = e; }
        }
    }
    float w0 = 1.f, w1 = 0.f;
    if (e1 >= 0) {
        float ex = expf(v1 - v0);
        w0 = 1.0f / (1.0f + ex);
        w1 = ex * w0;
    }
    bool has1 = (e1 >= 0 && w1 > 0.f);
    int p0 = atomicAdd(&sCnt[e0], 1);
    int p1 = has1 ? atomicAdd(&sCnt[e1], 1) : -1;
    __syncthreads();
    if (tid < 8) sBase[tid] = atomicAdd(&g_cnt[tid], sCnt[tid]);
    __syncthreads();
    {
        int pos = sBase[e0] + p0;
        g_list[e0*NTOK + pos] = n;
        g_wl[e0*NTOK + pos]   = w0;
    }
    unsigned te = (unsigned)e0 | (255u << 8);
    float tw1 = 0.f;
    if (has1) {
        int pos = sBase[e1] + p1;
        g_list[e1*NTOK + pos] = n;
        g_wl[e1*NTOK + pos]   = w1;
        te = (unsigned)e0 | ((unsigned)e1 << 8);
        tw1 = w1;
    }
    g_te[n] = te; g_tw0[n] = w0; g_tw1[n] = tw1;

    float4 z4 = make_float4(0.f, 0.f, 0.f, 0.f);
    float4* o4 = (float4*)out;
    for (int i = n; i < NTOK*OUTD/4; i += NTOK) o4[i] = z4;
}

// ---------------- fused expert FFN v8: lanes=tokens, dup-weight broadcast ----------------
__global__ void __launch_bounds__(256) ffn_kernel(
    const float* __restrict__ x,  const float* __restrict__ bw,
    const float* __restrict__ W1, const float* __restrict__ b1,
    const float* __restrict__ W2, const float* __restrict__ b2,
    const float* __restrict__ A1, const float* __restrict__ B1,
    const float* __restrict__ A2, const float* __restrict__ B2,
    float* __restrict__ out)
{
    extern __shared__ float sm[];
    float* sH  = sm;                     // [416][66]; sX aliases rows 0..223
    float* sX  = sm;
    float* sW  = sH + 416*SSTR;          // 2 x 12288 duplicated double buffer
    float* sBw = sW + 24576;             // [64][4]
    float* sGw = sBw + 256;              // [64]
    int*   sTok = (int*)(sGw + 64);      // [64]

    int e = blockIdx.y;
    int cnt = g_cnt[e];
    int t0 = blockIdx.x * TTILE;
    if (t0 >= cnt) return;
    int nt = min(TTILE, cnt - t0);
    int tid = threadIdx.x;

    if (tid < TTILE) {
        int idx = t0 + min(tid, nt - 1);
        int tok = g_list[e*NTOK + idx];
        sTok[tid] = tok;
        sGw[tid]  = (tid < nt) ? g_wl[e*NTOK + idx] : 0.f;
        *(float4*)(sBw + tid*4) = *(const float4*)(bw + (size_t)tok*4);
    }
    __syncthreads();

    {   // gather x rows -> sX[c][t] (t contiguous); stage A1 -> sW
        int t = tid & 63, part = tid >> 6;
        int tok = sTok[t];
        const float4* src = (const float4*)(x + (size_t)tok*CIN) + part*12;
        #pragma unroll
        for (int i = 0; i < 12; i++) {
            float4 v = src[i];
            int c = part*48 + i*4;
            sX[(c+0)*SSTR+t]=v.x; sX[(c+1)*SSTR+t]=v.y;
            sX[(c+2)*SSTR+t]=v.z; sX[(c+3)*SSTR+t]=v.w;
        }
        const float4* a4 = (const float4*)(A1 + (size_t)e*6144);
        float4* w4 = (float4*)sW;
        for (int i = tid; i < 1536; i += 256) w4[i] = a4[i];
    }
    __syncthreads();

    // LoRA1: thread = (token, band); 4 ull accs (r packed in pairs)
    {
        int t = tid >> 2, b = tid & 3;
        const ull* A = (const ull*)(sW + b*1536);
        ull accp[4] = {0,0,0,0};
        for (int c = 0; c < CIN; c++) {
            float xv = sX[c*SSTR + t];
            ull xp = pk2(xv, xv);
            #pragma unroll
            for (int j = 0; j < 4; j++) fma2(accp[j], xp, A[c*4 + j]);
        }
        float scl = LSCALE * sBw[t*4 + b];
        #pragma unroll
        for (int j = 0; j < 4; j++) {
            float lo, hi; upk2(accp[j], lo, hi);
            sX[(CIN + b*8 + 2*j    )*SSTR + t] = scl*lo;
            sX[(CIN + b*8 + 2*j + 1)*SSTR + t] = scl*hi;
        }
    }
    __syncthreads();

    int warp = tid >> 5, lane = tid & 31;
    int row = tid >> 4, c4 = tid & 15;

    // ---- layer 1: [64,224] @ [224,384]; lane = token pair, warp = 48 cols ----
    ull acc1[48];
    #pragma unroll
    for (int j = 0; j < 48; j++) {
        float bv = b1[e*HID + warp*48 + j];
        acc1[j] = pk2(bv, bv);
    }
    const float* W1e = W1 + (size_t)e*CIN*HID;
    const float* B1e = B1 + (size_t)e*32*HID;
    float4 pr[6];
    {   // prologue: tile 0 (rows < 16 -> W1e), duplicated stores
        const float4* s4 = (const float4*)(W1e + (size_t)row*HID);
        #pragma unroll
        for (int i = 0; i < 6; i++) pr[i] = s4[c4 + 16*i];
        #pragma unroll
        for (int i = 0; i < 6; i++) {
            float* d = sW + row*768 + (c4 + 16*i)*8;
            *(float4*)(d)   = make_float4(pr[i].x, pr[i].x, pr[i].y, pr[i].y);
            *(float4*)(d+4) = make_float4(pr[i].z, pr[i].z, pr[i].w, pr[i].w);
        }
    }
    for (int kt = 0; kt < 14; kt++) {
        if (kt < 13) {
            int k = (kt+1)*16 + row;
            const float* src = (k < CIN) ? (W1e + (size_t)k*HID)
                                         : (B1e + (size_t)(k - CIN)*HID);
            const float4* s4 = (const float4*)src;
            #pragma unroll
            for (int i = 0; i < 6; i++) pr[i] = s4[c4 + 16*i];
        }
        __syncthreads();
        const float* Wb = sW + (kt & 1)*12288 + warp*96;
        #pragma unroll 4
        for (int kk = 0; kk < 16; kk++) {
            int k = kt*16 + kk;
            ull xv = *(const ull*)(sX + k*SSTR + 2*lane);
            const ulonglong2* wq = (const ulonglong2*)(Wb + kk*768);
            #pragma unroll
            for (int jq = 0; jq < 24; jq++) {
                ulonglong2 w2 = wq[jq];
                fma2(acc1[2*jq    ], xv, w2.x);
                fma2(acc1[2*jq + 1], xv, w2.y);
            }
        }
        if (kt < 13) {
            float* db = sW + ((kt+1) & 1)*12288 + row*768;
            #pragma unroll
            for (int i = 0; i < 6; i++) {
                float* d = db + (c4 + 16*i)*8;
                *(float4*)(d)   = make_float4(pr[i].x, pr[i].x, pr[i].y, pr[i].y);
                *(float4*)(d+4) = make_float4(pr[i].z, pr[i].z, pr[i].w, pr[i].w);
            }
        }
    }
    __syncthreads();   // all layer-1 reads of sX done before sH overwrite

    // exact GELU -> sH[h][t] (aliases sX); lane holds tokens 2l,2l+1
    #pragma unroll
    for (int j = 0; j < 48; j++) {
        float lo, hi; upk2(acc1[j], lo, hi);
        float g0 = lo * 0.5f * (1.0f + erff(lo * 0.70710678118654752f));
        float g1 = hi * 0.5f * (1.0f + erff(hi * 0.70710678118654752f));
        int h = warp*48 + j;
        *(ull*)(sH + h*SSTR + 2*lane) = pk2(g0, g1);
    }
    __syncthreads();

    // LoRA2: thread = (token, band)
    {
        int t = tid >> 2, b = tid & 3;
        const ull* A = (const ull*)(A2 + ((size_t)e*4 + b)*HID*8);
        ull accp[4] = {0,0,0,0};
        for (int hh = 0; hh < HID; hh++) {
            float hv = sH[hh*SSTR + t];
            ull xp = pk2(hv, hv);
            #pragma unroll
            for (int j = 0; j < 4; j++) fma2(accp[j], xp, A[hh*4 + j]);
        }
        float scl = LSCALE * sBw[t*4 + b];
        #pragma unroll
        for (int j = 0; j < 4; j++) {
            float lo, hi; upk2(accp[j], lo, hi);
            sH[(HID + b*8 + 2*j    )*SSTR + t] = scl*lo;
            sH[(HID + b*8 + 2*j + 1)*SSTR + t] = scl*hi;
        }
    }

    // ---- layer 2: [64,416] @ [416,192]; warp = 24 cols ----
    ull acc2[24];
    #pragma unroll
    for (int j = 0; j < 24; j++) {
        float bv = b2[e*OUTD + warp*24 + j];
        acc2[j] = pk2(bv, bv);
    }
    const float* W2e = W2 + (size_t)e*HID*OUTD;
    const float* B2e = B2 + (size_t)e*32*OUTD;
    float4 qr[3];
    {   // prologue: tile 0
        const float4* s4 = (const float4*)(W2e + (size_t)row*OUTD);
        #pragma unroll
        for (int i = 0; i < 3; i++) qr[i] = s4[c4 + 16*i];
        #pragma unroll
        for (int i = 0; i < 3; i++) {
            float* d = sW + row*384 + (c4 + 16*i)*8;
            *(float4*)(d)   = make_float4(qr[i].x, qr[i].x, qr[i].y, qr[i].y);
            *(float4*)(d+4) = make_float4(qr[i].z, qr[i].z, qr[i].w, qr[i].w);
        }
    }
    for (int kt = 0; kt < 26; kt++) {
        if (kt < 25) {
            int k = (kt+1)*16 + row;
            const float* src = (k < HID) ? (W2e + (size_t)k*OUTD)
                                         : (B2e + (size_t)(k - HID)*OUTD);
            const float4* s4 = (const float4*)src;
            #pragma unroll
            for (int i = 0; i < 3; i++) qr[i] = s4[c4 + 16*i];
        }
        __syncthreads();
        const float* Wb = sW + (kt & 1)*12288 + warp*48;
        #pragma unroll 4
        for (int kk = 0; kk < 16; kk++) {
            int k = kt*16 + kk;
            ull xv = *(const ull*)(sH + k*SSTR + 2*lane);
            const ulonglong2* wq = (const ulonglong2*)(Wb + kk*384);
            #pragma unroll
            for (int jq = 0; jq < 12; jq++) {
                ulonglong2 w2 = wq[jq];
                fma2(acc2[2*jq    ], xv, w2.x);
                fma2(acc2[2*jq + 1], xv, w2.y);
            }
        }
        if (kt < 25) {
            float* db = sW + ((kt+1) & 1)*12288 + row*384;
            #pragma unroll
            for (int i = 0; i < 3; i++) {
                float* d = db + (c4 + 16*i)*8;
                *(float4*)(d)   = make_float4(qr[i].x, qr[i].x, qr[i].y, qr[i].y);
                *(float4*)(d+4) = make_float4(qr[i].z, qr[i].z, qr[i].w, qr[i].w);
            }
        }
    }
    // epilogue: lane's tokens 2l, 2l+1; cols warp*24..+23
    {
        int ta = 2*lane, tb = 2*lane + 1;
        bool va = (ta < nt), vb = (tb < nt);
        int toka = sTok[ta], tokb = sTok[tb];
        float ga = sGw[ta],  gb = sGw[tb];
        #pragma unroll
        for (int j = 0; j < 24; j++) {
            float lo, hi; upk2(acc2[j], lo, hi);
            int col = warp*24 + j;
            if (va) atomicAdd(&out[(size_t)toka*OUTD + col], ga*lo);
            if (vb) atomicAdd(&out[(size_t)tokb*OUTD + col], gb*hi);
        }
    }
}

// ---------------- deterministic loss ----------------
__global__ void __launch_bounds__(1024) loss_kernel(float* out, int out_size) {
    __shared__ float sI[8][32], sL[8][32];
    int tid = threadIdx.x, lane = tid & 31, warp = tid >> 5;
    float imp[8] = {0,0,0,0,0,0,0,0}, ld[8] = {0,0,0,0,0,0,0,0};
    for (int n = tid; n < NTOK; n += 1024) {
        unsigned te = g_te[n];
        int e0 = te & 255u, e1 = (te >> 8) & 255u;
        imp[e0] += g_tw0[n]; ld[e0] += 1.f;
        if (e1 != 255) { imp[e1] += g_tw1[n]; ld[e1] += 1.f; }
    }
    #pragma unroll
    for (int e = 0; e < 8; e++) {
        #pragma unroll
        for (int o = 16; o; o >>= 1) {
            imp[e] += __shfl_xor_sync(0xffffffffu, imp[e], o);
            ld[e]  += __shfl_xor_sync(0xffffffffu, ld[e],  o);
        }
        if (lane == 0) { sI[e][warp] = imp[e]; sL[e][warp] = ld[e]; }
    }
    __syncthreads();
    if (tid == 0) {
        float I[8], L[8], mi = 0.f, ml = 0.f;
        for (int e = 0; e < 8; e++) {
            float a = 0.f, b = 0.f;
            for (int w = 0; w < 32; w++) { a += sI[e][w]; b += sL[e][w]; }
            I[e] = a; L[e] = b; mi += a; ml += b;
        }
        mi *= 0.125f; ml *= 0.125f;
        float vi = 0.f, vl = 0.f;
        for (int e = 0; e < 8; e++) {
            float di = I[e] - mi; vi += di*di;
            float dl = L[e] - ml; vl += dl*dl;
        }
        vi *= 0.125f; vl *= 0.125f;
        float loss = (vi / (mi*mi + 1e-10f) + vl / (ml*ml + 1e-10f)) * 0.01f;
        if (out_size > NTOK*OUTD) out[NTOK*OUTD] = loss;
    }
    for (int i = NTOK*OUTD + 1 + tid; i < out_size; i += 1024) out[i] = 0.f;
}

// ---------------- launch ----------------
extern "C" void kernel_launch(void* const* d_in, const int* in_sizes, int n_in,
                              void* d_out, int out_size) {
    const float* x     = (const float*)d_in[0];
    const float* bw    = (const float*)d_in[1];
    const float* xprev = (const float*)d_in[2];
    const float* Wz    = (const float*)d_in[3];
    const float* lng   = (const float*)d_in[4];
    const float* lnb   = (const float*)d_in[5];
    const float* Wg    = (const float*)d_in[6];
    const float* bg    = (const float*)d_in[7];
    const float* W1    = (const float*)d_in[8];
    const float* b1    = (const float*)d_in[9];
    const float* W2    = (const float*)d_in[10];
    const float* b2    = (const float*)d_in[11];
    const float* A1    = (const float*)d_in[12];
    const float* B1    = (const float*)d_in[13];
    const float* A2    = (const float*)d_in[14];
    const float* B2    = (const float*)d_in[15];
    float* out = (float*)d_out;

    const size_t GATE_SMEM = (size_t)(12288 + 2322 + 258 + 258 + 8 + 32*192) * 4;
    const size_t FFN_SMEM  = (size_t)(416*SSTR + 24576 + 256 + 64 + 64) * 4;
    cudaFuncSetAttribute(gate_kernel, cudaFuncAttributeMaxDynamicSharedMemorySize, (int)GATE_SMEM);
    cudaFuncSetAttribute(ffn_kernel,  cudaFuncAttributeMaxDynamicSharedMemorySize, (int)FFN_SMEM);

    init_kernel<<<1, 32>>>();
    gate_kernel<<<NTOK/32, 1024, GATE_SMEM>>>(x, xprev, Wz, lng, lnb, Wg, bg);
    select_kernel<<<NE, 1024>>>();
    route_kernel<<<NTOK/256, 256>>>(out);
    ffn_kernel<<<dim3(NTOK/TTILE, NE), 256, FFN_SMEM>>>(x, bw, W1, b1, W2, b2,
                                                        A1, B1, A2, B2, out);
    loss_kernel<<<1, 1024>>>(out, out_size);
}

// round 9
// speedup vs baseline: 1.2379x; 1.2379x over previous
#include <cuda_runtime.h>
#include <math.h>
#include <stdint.h>

#define NTOK 65536
#define CIN 192
#define HID 384
#define OUTD 192
#define NE 8
#define KCAP 10240
#define TTILE 32
#define LSCALE 2.0f  /* alpha/r = 16/8 */

// FFN smem layout (floats)
#define XSTR 228           /* x split stride: K1=224 rows + pad */
#define HSTR 420           /* h split stride: K2=416 rows + pad */
#define OFF_XL   7296      /* 32*228 */
#define OFF_A1   14592
#define OFF_HL   13440     /* 32*420 */
#define OFF_WB   26880
#define WBUF_SZ  12544     /* per buffer: hi(6272)+lo(6272) */
#define WLO      6272
#define W1STR    392
#define W2STR    200
#define OFF_BW   51968
#define OFF_GW   52096
#define OFF_TOK  52128
#define FFN_FLOATS 52160

__device__ __forceinline__ void tf32split(float x, float& h, float& l) {
    unsigned hb; asm("cvt.rna.tf32.f32 %0, %1;" : "=r"(hb) : "f"(x));
    float hf = __uint_as_float(hb);
    float lf = x - hf;
    unsigned lb; asm("cvt.rna.tf32.f32 %0, %1;" : "=r"(lb) : "f"(lf));
    h = hf; l = __uint_as_float(lb);
}
__device__ __forceinline__ void mma8(float* d, const unsigned* a, unsigned b0, unsigned b1) {
    asm("mma.sync.aligned.m16n8k8.row.col.f32.tf32.tf32.f32 "
        "{%0,%1,%2,%3},{%4,%5,%6,%7},{%8,%9},{%0,%1,%2,%3};"
        : "+f"(d[0]), "+f"(d[1]), "+f"(d[2]), "+f"(d[3])
        : "r"(a[0]), "r"(a[1]), "r"(a[2]), "r"(a[3]), "r"(b0), "r"(b1));
}

// ---------------- device scratch ----------------
__device__ float    g_logits[NE * NTOK];
__device__ unsigned g_mask[NTOK];
__device__ int      g_cnt[NE];
__device__ int      g_list[NE * NTOK];
__device__ float    g_wl[NE * NTOK];
__device__ unsigned g_te[NTOK];
__device__ float    g_tw0[NTOK];
__device__ float    g_tw1[NTOK];

__global__ void init_kernel() {
    if (threadIdx.x < NE) g_cnt[threadIdx.x] = 0;
}

// ---------------- gate: features + LN + logits ----------------
__global__ void __launch_bounds__(1024) gate_kernel(
    const float* __restrict__ x, const float* __restrict__ xprev,
    const float* __restrict__ Wz, const float* __restrict__ lng,
    const float* __restrict__ lnb, const float* __restrict__ Wg,
    const float* __restrict__ bg)
{
    extern __shared__ float sm[];
    float* sWz = sm;            // 12288
    float* sWg = sWz + 12288;   // 258*9 padded
    float* sg  = sWg + 2322;
    float* sb  = sg + 258;
    float* sbg = sb + 258;
    float* sX  = sbg + 8;

    int tid = threadIdx.x, lane = tid & 31, warp = tid >> 5;
    int n = blockIdx.x * 32 + warp;

    for (int i = tid; i < 12288; i += 1024) sWz[i] = Wz[i];
    for (int i = tid; i < 2064;  i += 1024) sWg[(i >> 3)*9 + (i & 7)] = Wg[i];
    for (int i = tid; i < 258;   i += 1024) { sg[i] = lng[i]; sb[i] = lnb[i]; }
    if (tid < 8) sbg[tid] = bg[tid];

    float xr[6];
    #pragma unroll
    for (int i = 0; i < 6; i++) {
        xr[i] = x[(size_t)n*CIN + lane + 32*i];
        sX[warp*CIN + lane + 32*i] = xr[i];
    }
    float s = 0.f, ss = 0.f;
    #pragma unroll
    for (int i = 0; i < 6; i++) {
        float a = fabsf(xr[i] - xprev[(size_t)n*CIN + lane + 32*i]);
        s += a; ss += a*a;
    }
    #pragma unroll
    for (int o = 16; o; o >>= 1) {
        s  += __shfl_xor_sync(0xffffffffu, s, o);
        ss += __shfl_xor_sync(0xffffffffu, ss, o);
    }
    float dmean = s * (1.0f/192.0f);
    float dvar  = fmaxf((ss - s*dmean) * (1.0f/191.0f), 0.f);
    float mu = log1pf(dmean), sd = log1pf(sqrtf(dvar));

    __syncthreads();

    float z0 = 0.f, z1 = 0.f;
    for (int c = 0; c < CIN; c++) {
        float xv = sX[warp*CIN + c];
        z0 = fmaf(xv, sWz[c*64 + lane],      z0);
        z1 = fmaf(xv, sWz[c*64 + lane + 32], z1);
    }
    float sa = z0 + z1, s2 = z0*z0 + z1*z1;
    #pragma unroll
    for (int i = 0; i < 6; i++) { sa += xr[i]; s2 += xr[i]*xr[i]; }
    if (lane == 0) { sa += mu + sd; s2 += mu*mu + sd*sd; }
    #pragma unroll
    for (int o = 16; o; o >>= 1) {
        sa += __shfl_xor_sync(0xffffffffu, sa, o);
        s2 += __shfl_xor_sync(0xffffffffu, s2, o);
    }
    float m_   = sa * (1.0f/258.0f);
    float rstd = rsqrtf(s2 * (1.0f/258.0f) - m_*m_ + 1e-5f);

    float acc[8] = {0,0,0,0,0,0,0,0};
    #pragma unroll
    for (int i = 0; i < 6; i++) {
        int idx = lane + 32*i;
        float nv = (xr[i] - m_)*rstd*sg[idx] + sb[idx];
        #pragma unroll
        for (int e = 0; e < 8; e++) acc[e] = fmaf(nv, sWg[idx*9 + e], acc[e]);
    }
    {
        int idx = 192 + lane;
        float nv = (z0 - m_)*rstd*sg[idx] + sb[idx];
        #pragma unroll
        for (int e = 0; e < 8; e++) acc[e] = fmaf(nv, sWg[idx*9 + e], acc[e]);
        idx = 224 + lane;
        nv = (z1 - m_)*rstd*sg[idx] + sb[idx];
        #pragma unroll
        for (int e = 0; e < 8; e++) acc[e] = fmaf(nv, sWg[idx*9 + e], acc[e]);
    }
    if (lane == 0) {
        float nv = (mu - m_)*rstd*sg[256] + sb[256];
        #pragma unroll
        for (int e = 0; e < 8; e++) acc[e] = fmaf(nv, sWg[256*9 + e], acc[e]);
        nv = (sd - m_)*rstd*sg[257] + sb[257];
        #pragma unroll
        for (int e = 0; e < 8; e++) acc[e] = fmaf(nv, sWg[257*9 + e], acc[e]);
    }
    #pragma unroll
    for (int e = 0; e < 8; e++) {
        #pragma unroll
        for (int o = 16; o; o >>= 1) acc[e] += __shfl_xor_sync(0xffffffffu, acc[e], o);
    }
    if (lane == 0) {
        #pragma unroll
        for (int e = 0; e < 8; e++) g_logits[e*NTOK + n] = acc[e] + sbg[e];
        g_mask[n] = 0u;
    }
}

// ---------------- expert-choice: radix select top-K per expert ----------------
__device__ __forceinline__ unsigned f2key(float f) {
    unsigned u = __float_as_uint(f);
    return (u & 0x80000000u) ? ~u : (u | 0x80000000u);
}

__global__ void __launch_bounds__(1024) select_kernel() {
    __shared__ unsigned hist[256];
    __shared__ unsigned sh_digit, sh_need;
    __shared__ int ccount[64];
    __shared__ int cbase[64];

    int e = blockIdx.x, tid = threadIdx.x;
    int lane = tid & 31, warp = tid >> 5;
    const float* base = g_logits + (size_t)e * NTOK;

    unsigned prefix = 0, pmask = 0, need = KCAP;
    for (int pass = 0; pass < 4; pass++) {
        int shift = 24 - pass*8;
        if (tid < 256) hist[tid] = 0;
        __syncthreads();
        for (int n = tid; n < NTOK; n += 1024) {
            unsigned k = f2key(base[n]);
            bool act = ((k & pmask) == prefix);
            unsigned dg = act ? ((k >> shift) & 255u) : 0xffffffffu;
            unsigned peers = __match_any_sync(0xffffffffu, dg);
            if (act && (__ffs(peers) - 1) == lane)
                atomicAdd(&hist[dg], (unsigned)__popc(peers));
        }
        __syncthreads();
        if (tid == 0) {
            unsigned cum = 0; int d = 255;
            for (; d > 0; d--) {
                unsigned h = hist[d];
                if (cum + h >= need) break;
                cum += h;
            }
            sh_digit = (unsigned)d;
            sh_need  = need - cum;
        }
        __syncthreads();
        prefix |= sh_digit << shift;
        pmask  |= 0xFFu << shift;
        need    = sh_need;
        __syncthreads();
    }
    unsigned thr = prefix;
    int r = (int)need;

    for (int n = tid; n < NTOK; n += 1024)
        if (f2key(base[n]) > thr) atomicOr(&g_mask[n], 1u << e);

    for (int c = warp; c < 64; c += 32) {
        int cnt = 0;
        for (int s = 0; s < 32; s++) {
            int n = c*1024 + s*32 + lane;
            cnt += (f2key(base[n]) == thr);
        }
        #pragma unroll
        for (int o = 16; o; o >>= 1) cnt += __shfl_xor_sync(0xffffffffu, cnt, o);
        if (lane == 0) ccount[c] = cnt;
    }
    __syncthreads();
    if (tid == 0) {
        int run = 0;
        for (int c = 0; c < 64; c++) { cbase[c] = run; run += ccount[c]; }
    }
    __syncthreads();
    for (int c = warp; c < 64; c += 32) {
        int rank = cbase[c];
        if (rank >= r) continue;
        for (int s = 0; s < 32; s++) {
            int n = c*1024 + s*32 + lane;
            bool p = (f2key(base[n]) == thr);
            unsigned bal = __ballot_sync(0xffffffffu, p);
            int myrank = rank + __popc(bal & ((1u << lane) - 1u));
            if (p && myrank < r) atomicOr(&g_mask[n], 1u << e);
            rank += __popc(bal);
        }
    }
}

// ---------------- routing (block-aggregated dispatch) ----------------
__global__ void __launch_bounds__(256) route_kernel(float* __restrict__ out) {
    __shared__ int sCnt[8], sBase[8];
    int tid = threadIdx.x;
    int n = blockIdx.x * 256 + tid;
    if (tid < 8) sCnt[tid] = 0;
    __syncthreads();

    float l[8];
    #pragma unroll
    for (int e = 0; e < 8; e++) l[e] = g_logits[e*NTOK + n];
    unsigned m = g_mask[n];
    if (m == 0u) {
        int best = 0; float bv = l[0];
        #pragma unroll
        for (int e = 1; e < 8; e++) if (l[e] > bv) { bv = l[e]; best = e; }
        m = 1u << best;
    }
    int e0 = -1, e1 = -1; float v0 = -INFINITY, v1 = -INFINITY;
    #pragma unroll
    for (int e = 0; e < 8; e++) {
        if ((m >> e) & 1u) {
            float f = l[e];
            if (f > v0)      { v1 = v0; e1 = e0; v0 = f; e0 = e; }
            else if (f > v1) { v1 = f; e1 = e; }
        }
    }
    float w0 = 1.f, w1 = 0.f;
    if (e1 >= 0) {
        float ex = expf(v1 - v0);
        w0 = 1.0f / (1.0f + ex);
        w1 = ex * w0;
    }
    bool has1 = (e1 >= 0 && w1 > 0.f);
    int p0 = atomicAdd(&sCnt[e0], 1);
    int p1 = has1 ? atomicAdd(&sCnt[e1], 1) : -1;
    __syncthreads();
    if (tid < 8) sBase[tid] = atomicAdd(&g_cnt[tid], sCnt[tid]);
    __syncthreads();
    {
        int pos = sBase[e0] + p0;
        g_list[e0*NTOK + pos] = n;
        g_wl[e0*NTOK + pos]   = w0;
    }
    unsigned te = (unsigned)e0 | (255u << 8);
    float tw1 = 0.f;
    if (has1) {
        int pos = sBase[e1] + p1;
        g_list[e1*NTOK + pos] = n;
        g_wl[e1*NTOK + pos]   = w1;
        te = (unsigned)e0 | ((unsigned)e1 << 8);
        tw1 = w1;
    }
    g_te[n] = te; g_tw0[n] = w0; g_tw1[n] = tw1;

    float4 z4 = make_float4(0.f, 0.f, 0.f, 0.f);
    float4* o4 = (float4*)out;
    for (int i = n; i < NTOK*OUTD/4; i += NTOK) o4[i] = z4;
}

// ---------------- fused expert FFN v9: tf32 tensor-core split GEMMs ----------------
__global__ void __launch_bounds__(256) ffn_kernel(
    const float* __restrict__ x,  const float* __restrict__ bw,
    const float* __restrict__ W1, const float* __restrict__ b1,
    const float* __restrict__ W2, const float* __restrict__ b2,
    const float* __restrict__ A1, const float* __restrict__ B1,
    const float* __restrict__ A2, const float* __restrict__ B2,
    float* __restrict__ out)
{
    extern __shared__ float sm[];
    float* sBw = sm + OFF_BW;
    float* sGw = sm + OFF_GW;
    int*   sTok = (int*)(sm + OFF_TOK);

    int e = blockIdx.y;
    int cnt = g_cnt[e];
    int t0 = blockIdx.x * TTILE;
    if (t0 >= cnt) return;
    int nt = min(TTILE, cnt - t0);
    int tid = threadIdx.x;

    if (tid < TTILE) {
        int idx = t0 + min(tid, nt - 1);
        int tok = g_list[e*NTOK + idx];
        sTok[tid] = tok;
        sGw[tid]  = (tid < nt) ? g_wl[e*NTOK + idx] : 0.f;
        *(float4*)(sBw + tid*4) = *(const float4*)(bw + (size_t)tok*4);
    }
    __syncthreads();

    {   // gather x -> split [tok][k]; stage A1 raw
        int t = tid & 31, part = tid >> 5;   // 8 parts x 24 cols
        int tok = sTok[t];
        const float4* src = (const float4*)(x + (size_t)tok*CIN) + part*6;
        #pragma unroll
        for (int i = 0; i < 6; i++) {
            float4 v = src[i];
            int c = part*24 + i*4;
            float h0,l0,h1,l1,h2,l2,h3,l3;
            tf32split(v.x,h0,l0); tf32split(v.y,h1,l1);
            tf32split(v.z,h2,l2); tf32split(v.w,h3,l3);
            *(float4*)(sm + t*XSTR + c)          = make_float4(h0,h1,h2,h3);
            *(float4*)(sm + OFF_XL + t*XSTR + c) = make_float4(l0,l1,l2,l3);
        }
        const float4* a4 = (const float4*)(A1 + (size_t)e*6144);
        float4* w4 = (float4*)(sm + OFF_A1);
        for (int i = tid; i < 1536; i += 256) w4[i] = a4[i];
    }
    __syncthreads();

    // LoRA1: thread = (token, band, r-half); x = xh + xl
    {
        int t = tid >> 3, b = (tid >> 1) & 3, rh = tid & 1, r0 = rh*4;
        const float* A = sm + OFF_A1 + b*1536 + r0;
        float acc[4] = {0,0,0,0};
        for (int c = 0; c < CIN; c++) {
            float xv = sm[t*XSTR + c] + sm[OFF_XL + t*XSTR + c];
            float4 av = *(const float4*)(A + c*8);
            acc[0] = fmaf(xv, av.x, acc[0]); acc[1] = fmaf(xv, av.y, acc[1]);
            acc[2] = fmaf(xv, av.z, acc[2]); acc[3] = fmaf(xv, av.w, acc[3]);
        }
        float scl = LSCALE * sBw[t*4 + b];
        #pragma unroll
        for (int j = 0; j < 4; j++) {
            float h, l; tf32split(scl*acc[j], h, l);
            sm[t*XSTR + 192 + b*8 + r0 + j]          = h;
            sm[OFF_XL + t*XSTR + 192 + b*8 + r0 + j] = l;
        }
    }

    int warp = tid >> 5, lane = tid & 31;
    int g = lane >> 2, kq = lane & 3;
    int row = tid >> 4, c4 = tid & 15;
    const unsigned* uX = (const unsigned*)sm;

    // ---- layer 1: [32,224]x[224,384]; warp = 2 M-tiles x 48 cols ----
    float d1[2][6][4];
    #pragma unroll
    for (int nj = 0; nj < 6; nj++) {
        int col = warp*48 + nj*8 + 2*kq;
        float b0v = b1[e*HID + col], b1v = b1[e*HID + col + 1];
        #pragma unroll
        for (int mt = 0; mt < 2; mt++) {
            d1[mt][nj][0] = b0v; d1[mt][nj][1] = b1v;
            d1[mt][nj][2] = b0v; d1[mt][nj][3] = b1v;
        }
    }
    const float* W1e = W1 + (size_t)e*CIN*HID;
    const float* B1e = B1 + (size_t)e*32*HID;
    {   // prologue: stage tile 0 split
        const float4* s4 = (const float4*)(W1e + (size_t)row*HID);
        float* Wh = sm + OFF_WB;
        #pragma unroll
        for (int i = 0; i < 6; i++) {
            float4 v = s4[c4 + 16*i];
            float h0,l0,h1,l1,h2,l2,h3,l3;
            tf32split(v.x,h0,l0); tf32split(v.y,h1,l1);
            tf32split(v.z,h2,l2); tf32split(v.w,h3,l3);
            int off = row*W1STR + 4*c4 + 64*i;
            *(float4*)(Wh + off)       = make_float4(h0,h1,h2,h3);
            *(float4*)(Wh + WLO + off) = make_float4(l0,l1,l2,l3);
        }
    }
    float4 pr[6];
    for (int kt = 0; kt < 14; kt++) {
        if (kt < 13) {
            int k = (kt+1)*16 + row;
            const float* src = (k < CIN) ? (W1e + (size_t)k*HID)
                                         : (B1e + (size_t)(k - CIN)*HID);
            const float4* s4 = (const float4*)src;
            #pragma unroll
            for (int i = 0; i < 6; i++) pr[i] = s4[c4 + 16*i];
        }
        __syncthreads();
        const unsigned* Wh = (const unsigned*)(sm + OFF_WB + (kt&1)*WBUF_SZ);
        const unsigned* Wl = Wh + WLO;
        #pragma unroll
        for (int k8 = 0; k8 < 2; k8++) {
            int kb = kt*16 + k8*8;
            unsigned ah[2][4], al[2][4];
            #pragma unroll
            for (int mt = 0; mt < 2; mt++) {
                int base = (mt*16 + g)*XSTR + kb + kq;
                ah[mt][0] = uX[base];               al[mt][0] = uX[OFF_XL + base];
                ah[mt][1] = uX[base + 8*XSTR];      al[mt][1] = uX[OFF_XL + base + 8*XSTR];
                ah[mt][2] = uX[base + 4];           al[mt][2] = uX[OFF_XL + base + 4];
                ah[mt][3] = uX[base + 8*XSTR + 4];  al[mt][3] = uX[OFF_XL + base + 8*XSTR + 4];
            }
            #pragma unroll
            for (int nj = 0; nj < 6; nj++) {
                int o0 = (k8*8 + kq)*W1STR + warp*48 + nj*8 + g;
                int o1 = o0 + 4*W1STR;
                unsigned bh0 = Wh[o0], bh1 = Wh[o1];
                unsigned bl0 = Wl[o0], bl1 = Wl[o1];
                #pragma unroll
                for (int mt = 0; mt < 2; mt++) {
                    mma8(d1[mt][nj], ah[mt], bh0, bh1);
                    mma8(d1[mt][nj], ah[mt], bl0, bl1);
                    mma8(d1[mt][nj], al[mt], bh0, bh1);
                }
            }
        }
        if (kt < 13) {
            float* Wd = sm + OFF_WB + ((kt+1)&1)*WBUF_SZ;
            #pragma unroll
            for (int i = 0; i < 6; i++) {
                float h0,l0,h1,l1,h2,l2,h3,l3;
                tf32split(pr[i].x,h0,l0); tf32split(pr[i].y,h1,l1);
                tf32split(pr[i].z,h2,l2); tf32split(pr[i].w,h3,l3);
                int off = row*W1STR + 4*c4 + 64*i;
                *(float4*)(Wd + off)       = make_float4(h0,h1,h2,h3);
                *(float4*)(Wd + WLO + off) = make_float4(l0,l1,l2,l3);
            }
        }
    }
    __syncthreads();   // layer-1 X reads done; H overwrites region

    // exact GELU -> split H [tok][h]
    #pragma unroll
    for (int mt = 0; mt < 2; mt++)
        #pragma unroll
        for (int nj = 0; nj < 6; nj++) {
            int col = warp*48 + nj*8 + 2*kq;
            #pragma unroll
            for (int q = 0; q < 4; q++) {
                int t = mt*16 + g + (q >> 1)*8;
                int c = col + (q & 1);
                float v = d1[mt][nj][q];
                float gv = v * 0.5f * (1.0f + erff(v * 0.70710678118654752f));
                float h, l; tf32split(gv, h, l);
                sm[t*HSTR + c]          = h;
                sm[OFF_HL + t*HSTR + c] = l;
            }
        }
    __syncthreads();

    // LoRA2: thread = (token, band, r-half); h = hh + hl
    {
        int t = tid >> 3, b = (tid >> 1) & 3, rh = tid & 1, r0 = rh*4;
        const float* A = A2 + ((size_t)e*4 + b)*HID*8 + r0;
        float acc[4] = {0,0,0,0};
        for (int hh = 0; hh < HID; hh++) {
            float hv = sm[t*HSTR + hh] + sm[OFF_HL + t*HSTR + hh];
            float4 av = *(const float4*)(A + hh*8);
            acc[0] = fmaf(hv, av.x, acc[0]); acc[1] = fmaf(hv, av.y, acc[1]);
            acc[2] = fmaf(hv, av.z, acc[2]); acc[3] = fmaf(hv, av.w, acc[3]);
        }
        float scl = LSCALE * sBw[t*4 + b];
        #pragma unroll
        for (int j = 0; j < 4; j++) {
            float h, l; tf32split(scl*acc[j], h, l);
            sm[t*HSTR + 384 + b*8 + r0 + j]          = h;
            sm[OFF_HL + t*HSTR + 384 + b*8 + r0 + j] = l;
        }
    }

    // ---- layer 2: [32,416]x[416,192]; warp = 2 M-tiles x 24 cols ----
    float d2[2][3][4];
    #pragma unroll
    for (int nj = 0; nj < 3; nj++) {
        int col = warp*24 + nj*8 + 2*kq;
        float b0v = b2[e*OUTD + col], b1v = b2[e*OUTD + col + 1];
        #pragma unroll
        for (int mt = 0; mt < 2; mt++) {
            d2[mt][nj][0] = b0v; d2[mt][nj][1] = b1v;
            d2[mt][nj][2] = b0v; d2[mt][nj][3] = b1v;
        }
    }
    const float* W2e = W2 + (size_t)e*HID*OUTD;
    const float* B2e = B2 + (size_t)e*32*OUTD;
    {   // prologue: stage tile 0
        const float4* s4 = (const float4*)(W2e + (size_t)row*OUTD);
        float* Wh = sm + OFF_WB;
        #pragma unroll
        for (int i = 0; i < 3; i++) {
            float4 v = s4[c4 + 16*i];
            float h0,l0,h1,l1,h2,l2,h3,l3;
            tf32split(v.x,h0,l0); tf32split(v.y,h1,l1);
            tf32split(v.z,h2,l2); tf32split(v.w,h3,l3);
            int off = row*W2STR + 4*c4 + 64*i;
            *(float4*)(Wh + off)       = make_float4(h0,h1,h2,h3);
            *(float4*)(Wh + WLO + off) = make_float4(l0,l1,l2,l3);
        }
    }
    float4 qr[3];
    for (int kt = 0; kt < 26; kt++) {
        if (kt < 25) {
            int k = (kt+1)*16 + row;
            const float* src = (k < HID) ? (W2e + (size_t)k*OUTD)
                                         : (B2e + (size_t)(k - HID)*OUTD);
            const float4* s4 = (const float4*)src;
            #pragma unroll
            for (int i = 0; i < 3; i++) qr[i] = s4[c4 + 16*i];
        }
        __syncthreads();
        const unsigned* Wh = (const unsigned*)(sm + OFF_WB + (kt&1)*WBUF_SZ);
        const unsigned* Wl = Wh + WLO;
        #pragma unroll
        for (int k8 = 0; k8 < 2; k8++) {
            int kb = kt*16 + k8*8;
            unsigned ah[2][4], al[2][4];
            #pragma unroll
            for (int mt = 0; mt < 2; mt++) {
                int base = (mt*16 + g)*HSTR + kb + kq;
                ah[mt][0] = uX[base];               al[mt][0] = uX[OFF_HL + base];
                ah[mt][1] = uX[base + 8*HSTR];      al[mt][1] = uX[OFF_HL + base + 8*HSTR];
                ah[mt][2] = uX[base + 4];           al[mt][2] = uX[OFF_HL + base + 4];
                ah[mt][3] = uX[base + 8*HSTR + 4];  al[mt][3] = uX[OFF_HL + base + 8*HSTR + 4];
            }
            #pragma unroll
            for (int nj = 0; nj < 3; nj++) {
                int o0 = (k8*8 + kq)*W2STR + warp*24 + nj*8 + g;
                int o1 = o0 + 4*W2STR;
                unsigned bh0 = Wh[o0], bh1 = Wh[o1];
                unsigned bl0 = Wl[o0], bl1 = Wl[o1];
                #pragma unroll
                for (int mt = 0; mt < 2; mt++) {
                    mma8(d2[mt][nj], ah[mt], bh0, bh1);
                    mma8(d2[mt][nj], ah[mt], bl0, bl1);
                    mma8(d2[mt][nj], al[mt], bh0, bh1);
                }
            }
        }
        if (kt < 25) {
            float* Wd = sm + OFF_WB + ((kt+1)&1)*WBUF_SZ;
            #pragma unroll
            for (int i = 0; i < 3; i++) {
                float h0,l0,h1,l1,h2,l2,h3,l3;
                tf32split(qr[i].x,h0,l0); tf32split(qr[i].y,h1,l1);
                tf32split(qr[i].z,h2,l2); tf32split(qr[i].w,h3,l3);
                int off = row*W2STR + 4*c4 + 64*i;
                *(float4*)(Wd + off)       = make_float4(h0,h1,h2,h3);
                *(float4*)(Wd + WLO + off) = make_float4(l0,l1,l2,l3);
            }
        }
    }
    // epilogue: atomicAdd (each out element written <= 2x -> commutative)
    #pragma unroll
    for (int mt = 0; mt < 2; mt++)
        #pragma unroll
        for (int nj = 0; nj < 3; nj++) {
            int col = warp*24 + nj*8 + 2*kq;
            #pragma unroll
            for (int q = 0; q < 4; q++) {
                int t = mt*16 + g + (q >> 1)*8;
                if (t < nt) {
                    int tok = sTok[t];
                    atomicAdd(&out[(size_t)tok*OUTD + col + (q & 1)],
                              sGw[t]*d2[mt][nj][q]);
                }
            }
        }
}

// ---------------- deterministic loss ----------------
__global__ void __launch_bounds__(1024) loss_kernel(float* out, int out_size) {
    __shared__ float sI[8][32], sL[8][32];
    int tid = threadIdx.x, lane = tid & 31, warp = tid >> 5;
    float imp[8] = {0,0,0,0,0,0,0,0}, ld[8] = {0,0,0,0,0,0,0,0};
    for (int n = tid; n < NTOK; n += 1024) {
        unsigned te = g_te[n];
        int e0 = te & 255u, e1 = (te >> 8) & 255u;
        imp[e0] += g_tw0[n]; ld[e0] += 1.f;
        if (e1 != 255) { imp[e1] += g_tw1[n]; ld[e1] += 1.f; }
    }
    #pragma unroll
    for (int e = 0; e < 8; e++) {
        #pragma unroll
        for (int o = 16; o; o >>= 1) {
            imp[e] += __shfl_xor_sync(0xffffffffu, imp[e], o);
            ld[e]  += __shfl_xor_sync(0xffffffffu, ld[e],  o);
        }
        if (lane == 0) { sI[e][warp] = imp[e]; sL[e][warp] = ld[e]; }
    }
    __syncthreads();
    if (tid == 0) {
        float I[8], L[8], mi = 0.f, ml = 0.f;
        for (int e = 0; e < 8; e++) {
            float a = 0.f, b = 0.f;
            for (int w = 0; w < 32; w++) { a += sI[e][w]; b += sL[e][w]; }
            I[e] = a; L[e] = b; mi += a; ml += b;
        }
        mi *= 0.125f; ml *= 0.125f;
        float vi = 0.f, vl = 0.f;
        for (int e = 0; e < 8; e++) {
            float di = I[e] - mi; vi += di*di;
            float dl = L[e] - ml; vl += dl*dl;
        }
        vi *= 0.125f; vl *= 0.125f;
        float loss = (vi / (mi*mi + 1e-10f) + vl / (ml*ml + 1e-10f)) * 0.01f;
        if (out_size > NTOK*OUTD) out[NTOK*OUTD] = loss;
    }
    for (int i = NTOK*OUTD + 1 + tid; i < out_size; i += 1024) out[i] = 0.f;
}

// ---------------- launch ----------------
extern "C" void kernel_launch(void* const* d_in, const int* in_sizes, int n_in,
                              void* d_out, int out_size) {
    const float* x     = (const float*)d_in[0];
    const float* bw    = (const float*)d_in[1];
    const float* xprev = (const float*)d_in[2];
    const float* Wz    = (const float*)d_in[3];
    const float* lng   = (const float*)d_in[4];
    const float* lnb   = (const float*)d_in[5];
    const float* Wg    = (const float*)d_in[6];
    const float* bg    = (const float*)d_in[7];
    const float* W1    = (const float*)d_in[8];
    const float* b1    = (const float*)d_in[9];
    const float* W2    = (const float*)d_in[10];
    const float* b2    = (const float*)d_in[11];
    const float* A1    = (const float*)d_in[12];
    const float* B1    = (const float*)d_in[13];
    const float* A2    = (const float*)d_in[14];
    const float* B2    = (const float*)d_in[15];
    float* out = (float*)d_out;

    const size_t GATE_SMEM = (size_t)(12288 + 2322 + 258 + 258 + 8 + 32*192) * 4;
    const size_t FFN_SMEM  = (size_t)FFN_FLOATS * 4;
    cudaFuncSetAttribute(gate_kernel, cudaFuncAttributeMaxDynamicSharedMemorySize, (int)GATE_SMEM);
    cudaFuncSetAttribute(ffn_kernel,  cudaFuncAttributeMaxDynamicSharedMemorySize, (int)FFN_SMEM);

    init_kernel<<<1, 32>>>();
    gate_kernel<<<NTOK/32, 1024, GATE_SMEM>>>(x, xprev, Wz, lng, lnb, Wg, bg);
    select_kernel<<<NE, 1024>>>();
    route_kernel<<<NTOK/256, 256>>>(out);
    ffn_kernel<<<dim3(NTOK/TTILE, NE), 256, FFN_SMEM>>>(x, bw, W1, b1, W2, b2,
                                                        A1, B1, A2, B2, out);
    loss_kernel<<<1, 1024>>>(out, out_size);
}